// round 2
// baseline (speedup 1.0000x reference)
#include <cuda_runtime.h>
#include <math.h>

// Problem constants
#define TS   2048
#define IIN  64
#define HD   512
#define NL   5
#define G4   (4*HD)

// Persistent-kernel partitioning
#define NB0  16      // blocks for layer 0 (128 rows each)
#define NB1  32      // blocks for layers 1..4 (64 rows each)
#define NT   512     // threads per block
#define TOTAL_BLOCKS (NB0 + 4*NB1)   // 144 <= 148 SMs -> all co-resident

// Shared memory sizing (floats):
//  layers1-4: 64*768 + 1024 + 64 + 64 + 16 = 50320
//  layer0   : 128*384 + 576 + 128 + 128 + 32 = 50016
#define SMEM_FLOATS 50320
#define SMEM_BYTES  (SMEM_FLOATS*4)

// Device scratch (allowed: __device__ globals, no runtime allocation)
__device__ float g_h[NL][TS][HD];     // per-layer hidden state history (20 MB)
__device__ int   g_cnt[NL][TS];       // per (layer,t) completion counters
__device__ float g_z[TS];
__device__ float g_wt[TS];
__device__ float g_part[32][HD];

__device__ __forceinline__ float sigf(float v){ return 1.0f/(1.0f + expf(-v)); }

// One layer's persistent worker.
// ROWS: gate rows owned by this block; NS: threads per row; K: full reduction
// length (IK + HD); KS: portion of K held in SMEM (rest streamed from L2);
// NU: hidden units owned (= ROWS/4); IK: input feature count for this layer.
template<int ROWS, int NS, int K, int KS, int NU, int IK>
__device__ void run_layer(int layer, int b, int nbPrev, int nbOwn,
                          const float* __restrict__ wih,
                          const float* __restrict__ whh,
                          const float* __restrict__ bih,
                          const float* __restrict__ bhh,
                          const float* __restrict__ x,
                          float* smem)
{
    const int tid = threadIdx.x;
    float* WS    = smem;                  // [ROWS][KS] weights
    float* sIn   = WS + ROWS*KS;          // [IK+HD] input vector (x_t ; h_{t-1})
    float* sGate = sIn + (IK + HD);       // [ROWS]
    float* sBias = sGate + ROWS;          // [ROWS]
    float* sC    = sBias + ROWS;          // [NU] cell state

    // ---- one-time: stage weight prefix [0,KS) into SMEM ----
    for (int idx = tid; idx < ROWS*KS; idx += NT){
        int r = idx / KS, k = idx - r*KS;
        int grow = (r/NU)*HD + b*NU + (r%NU);
        WS[idx] = (k < IK) ? wih[(size_t)grow*IK + k]
                           : whh[(size_t)grow*HD + (k - IK)];
    }
    if (tid < ROWS){
        int grow = (tid/NU)*HD + b*NU + (tid%NU);
        sBias[tid] = bih[grow] + bhh[grow];
    }
    if (tid < NU) sC[tid] = 0.0f;
    __syncthreads();

    const int lr = tid / NS;              // local row
    const int s  = tid % NS;              // K-slice id within row
    const int grow = (lr/NU)*HD + b*NU + (lr%NU);
    const float* wrow = WS + lr*KS + 4*s;
    const float* wg   = whh + (size_t)grow*HD - IK;  // index with k0 in [KS,K)
    constexpr int NC  = K  / (4*NS);      // total float4 chunks per thread
    constexpr int NCS = KS / (4*NS);      // chunks resident in SMEM (=24)

    float* hout = &g_h[layer][0][b*NU];

    for (int t = 0; t < TS; ++t){
        // ---- wait for dependencies (wavefront sync through L2 flags) ----
        if (tid == 0){
            if (layer > 0){ volatile int* p = &g_cnt[layer-1][t]; while (*p < nbPrev) {} }
            if (t > 0)    { volatile int* p = &g_cnt[layer][t-1]; while (*p < nbOwn) {} }
        }
        __syncthreads();

        // ---- gather input vector [x_t ; h_{t-1}] into SMEM ----
        if (IK == HD){
            sIn[tid]      = *((volatile const float*)&g_h[layer-1][t][tid]);
            sIn[HD + tid] = (t > 0) ? *((volatile const float*)&g_h[layer][t-1][tid]) : 0.0f;
        } else {
            if (tid < IK) sIn[tid] = x[t*IIN + tid];
            sIn[IK + tid] = (t > 0) ? *((volatile const float*)&g_h[0][t-1][tid]) : 0.0f;
        }
        __syncthreads();

        // ---- gate matvec: SMEM-resident prefix + L2-streamed suffix ----
        float a0 = 0.0f, a1 = 0.0f;
        #pragma unroll
        for (int c = 0; c < NCS; c += 2){
            float4 w0 = *reinterpret_cast<const float4*>(wrow + 4*NS*c);
            float4 v0 = *reinterpret_cast<const float4*>(sIn + 4*(s + NS*c));
            a0 = fmaf(w0.x, v0.x, a0); a0 = fmaf(w0.y, v0.y, a0);
            a0 = fmaf(w0.z, v0.z, a0); a0 = fmaf(w0.w, v0.w, a0);
            float4 w1 = *reinterpret_cast<const float4*>(wrow + 4*NS*(c+1));
            float4 v1 = *reinterpret_cast<const float4*>(sIn + 4*(s + NS*(c+1)));
            a1 = fmaf(w1.x, v1.x, a1); a1 = fmaf(w1.y, v1.y, a1);
            a1 = fmaf(w1.z, v1.z, a1); a1 = fmaf(w1.w, v1.w, a1);
        }
        #pragma unroll
        for (int c = NCS; c < NC; ++c){
            int k0 = 4*(s + NS*c);
            float4 w0 = __ldcg(reinterpret_cast<const float4*>(wg + k0));
            float4 v0 = *reinterpret_cast<const float4*>(sIn + k0);
            a0 = fmaf(w0.x, v0.x, a0); a0 = fmaf(w0.y, v0.y, a0);
            a0 = fmaf(w0.z, v0.z, a0); a0 = fmaf(w0.w, v0.w, a0);
        }
        float acc = a0 + a1;
        #pragma unroll
        for (int off = NS/2; off > 0; off >>= 1)
            acc += __shfl_xor_sync(0xffffffffu, acc, off);
        if (s == 0) sGate[lr] = acc + sBias[lr];
        __syncthreads();

        // ---- LSTM cell update for owned units; publish h ----
        if (tid < NU){
            float gi = sGate[tid];
            float gf = sGate[NU + tid];
            float gg = sGate[2*NU + tid];
            float go = sGate[3*NU + tid];
            float iv = sigf(gi), fv = sigf(gf), cv = tanhf(gg), ov = sigf(go);
            float cc = fv*sC[tid] + iv*cv;
            float hh = ov * tanhf(cc);
            sC[tid] = cc;
            hout[(size_t)t*HD + tid] = hh;
        }
        __threadfence();
        __syncthreads();
        if (tid == 0) atomicAdd(&g_cnt[layer][t], 1);
    }
}

__global__ void __launch_bounds__(NT, 1) lstm_kernel(
    const float* __restrict__ x,
    const float* __restrict__ w_ih0, const float* __restrict__ w_hh0,
    const float* __restrict__ b_ih0, const float* __restrict__ b_hh0,
    const float* __restrict__ w_ih,  const float* __restrict__ w_hh,
    const float* __restrict__ b_ih,  const float* __restrict__ b_hh)
{
    extern __shared__ float smem[];
    int bid = blockIdx.x;
    if (bid < NB0){
        // layer 0: 16 blocks x 128 rows, K=576 (64 input + 512 hidden), 384 in SMEM
        run_layer<128, 4, 576, 384, 32, IIN>(0, bid, 0, NB0,
            w_ih0, w_hh0, b_ih0, b_hh0, x, smem);
    } else {
        int r = bid - NB0;
        int layer = 1 + (r >> 5);
        int b = r & 31;
        size_t off = (size_t)(layer-1) * G4;
        // layers 1..4: 32 blocks x 64 rows, K=1024, 768 in SMEM, 256 streamed from L2
        run_layer<64, 8, 1024, 768, 16, HD>(layer, b,
            (layer == 1) ? NB0 : NB1, NB1,
            w_ih + off*HD, w_hh + off*HD, b_ih + off, b_hh + off, x, smem);
    }
}

// ---------------- epilogue: attention pooling ----------------

__global__ void k_zero(){
    int i = blockIdx.x*blockDim.x + threadIdx.x;
    if (i < NL*TS) (&g_cnt[0][0])[i] = 0;
}

__global__ void k_e(const float* __restrict__ wlin, const float* __restrict__ blin){
    int t = blockIdx.x;
    int tid = threadIdx.x;
    float a = 0.0f;
    for (int j = tid; j < HD; j += 128) a += g_h[NL-1][t][j] * wlin[j];
    #pragma unroll
    for (int off = 16; off; off >>= 1) a += __shfl_xor_sync(0xffffffffu, a, off);
    __shared__ float sr[4];
    if ((tid & 31) == 0) sr[tid >> 5] = a;
    __syncthreads();
    if (tid == 0) g_z[t] = tanhf(sr[0] + sr[1] + sr[2] + sr[3] + blin[0]);
}

__global__ void k_softmax(){
    int tid = threadIdx.x;
    __shared__ float sr[32];
    __shared__ float sbc;
    float z1 = g_z[tid], z2 = g_z[tid + 1024];
    float m = fmaxf(z1, z2);
    #pragma unroll
    for (int off = 16; off; off >>= 1) m = fmaxf(m, __shfl_xor_sync(0xffffffffu, m, off));
    if ((tid & 31) == 0) sr[tid >> 5] = m;
    __syncthreads();
    if (tid < 32){
        float v = sr[tid];
        #pragma unroll
        for (int off = 16; off; off >>= 1) v = fmaxf(v, __shfl_xor_sync(0xffffffffu, v, off));
        if (tid == 0) sbc = v;
    }
    __syncthreads();
    float mm = sbc;
    float e1 = expf(z1 - mm), e2 = expf(z2 - mm);
    float s = e1 + e2;
    #pragma unroll
    for (int off = 16; off; off >>= 1) s += __shfl_xor_sync(0xffffffffu, s, off);
    __syncthreads();
    if ((tid & 31) == 0) sr[tid >> 5] = s;
    __syncthreads();
    if (tid < 32){
        float v = sr[tid];
        #pragma unroll
        for (int off = 16; off; off >>= 1) v += __shfl_xor_sync(0xffffffffu, v, off);
        if (tid == 0) sbc = v;
    }
    __syncthreads();
    float inv = 1.0f / (sbc * (float)TS);
    g_wt[tid]        = e1 * inv;
    g_wt[tid + 1024] = e2 * inv;
}

__global__ void k_part(){
    int bb = blockIdx.x, tid = threadIdx.x;
    float a = 0.0f;
    int t0 = bb * 64;
    #pragma unroll 4
    for (int t = t0; t < t0 + 64; ++t) a += g_wt[t] * g_h[NL-1][t][tid];
    g_part[bb][tid] = a;
}

__global__ void k_final(float* __restrict__ out){
    int tid = threadIdx.x;
    float a = 0.0f;
    #pragma unroll
    for (int bb = 0; bb < 32; ++bb) a += g_part[bb][tid];
    out[tid] = a;
}

extern "C" void kernel_launch(void* const* d_in, const int* in_sizes, int n_in,
                              void* d_out, int out_size)
{
    const float* x     = (const float*)d_in[0];
    const float* w_ih0 = (const float*)d_in[1];
    const float* w_hh0 = (const float*)d_in[2];
    const float* b_ih0 = (const float*)d_in[3];
    const float* b_hh0 = (const float*)d_in[4];
    const float* w_ih  = (const float*)d_in[5];
    const float* w_hh  = (const float*)d_in[6];
    const float* b_ih  = (const float*)d_in[7];
    const float* b_hh  = (const float*)d_in[8];
    const float* w_lin = (const float*)d_in[9];
    const float* b_lin = (const float*)d_in[10];

    cudaFuncSetAttribute(lstm_kernel, cudaFuncAttributeMaxDynamicSharedMemorySize, SMEM_BYTES);

    k_zero<<<(NL*TS + 255)/256, 256>>>();
    lstm_kernel<<<TOTAL_BLOCKS, NT, SMEM_BYTES>>>(x, w_ih0, w_hh0, b_ih0, b_hh0,
                                                  w_ih, w_hh, b_ih, b_hh);
    k_e<<<TS, 128>>>(w_lin, b_lin);
    k_softmax<<<1, 1024>>>();
    k_part<<<32, 512>>>();
    k_final<<<1, 512>>>((float*)d_out);
}

// round 3
// speedup vs baseline: 1.1425x; 1.1425x over previous
#include <cuda_runtime.h>
#include <math.h>

// Problem constants
#define TS   2048
#define IIN  64
#define HD   512
#define NL   5

// Partitioning: layer0 -> 16 blocks x 128 rows; layers1..4 -> 32 blocks x 64 rows
#define NB0  16
#define NB1  32
#define NT   512
#define TOTAL_BLOCKS (NB0 + 4*NB1)   // 144 <= 148 SMs, 1 block/SM -> co-resident

// SMEM: layers1-4: 64*768 + 64 = 49216 floats ; layer0: 128*384 + 128 = 49280 floats
#define SMEM_BYTES (49280*4)

// Device scratch
__device__ float g_h[NL][TS][HD];     // hidden state history
__device__ int   g_flag[NL][64];      // per (layer, block) progress flags
__device__ float g_z[TS];
__device__ float g_wt[TS];
__device__ float g_part[32][HD];

__device__ __forceinline__ float sigf(float v){ return 1.0f/(1.0f + expf(-v)); }

__device__ __forceinline__ int ld_acq(const int* p){
    int v; asm volatile("ld.global.acquire.gpu.b32 %0, [%1];" : "=r"(v) : "l"(p) : "memory");
    return v;
}
__device__ __forceinline__ void st_rel(int* p, int v){
    asm volatile("st.global.release.gpu.b32 [%0], %1;" :: "l"(p), "r"(v) : "memory");
}

// ---------------- layer 0 : 16 blocks x 128 rows, K = 512(h) + 64(x) ----------------
__device__ void run_l0(int b, const float* __restrict__ x,
                       const float* __restrict__ wih0, const float* __restrict__ whh0,
                       const float* __restrict__ bih0, const float* __restrict__ bhh0,
                       float* sm)
{
    float* WS = sm;              // [128][384]  cols [0,384) of whh0 rows
    float* sG = sm + 128*384;    // [128] gate sums
    const int tid = threadIdx.x, warp = tid >> 5, lane = tid & 31;

    // Stage SMEM weights (h-cols [0,384))
    for (int idx = tid; idx < 128*384; idx += NT){
        int r = idx / 384, c = idx - r*384;
        int grow = (r >> 5)*HD + b*32 + (r & 31);
        WS[idx] = whh0[grow*HD + c];
    }
    // Register-resident suffix: h-cols [384,512) (float4/lane) + x-cols (float2/lane)
    float4 wh[8]; float2 wx[8];
    #pragma unroll
    for (int j = 0; j < 8; j++){
        int r = 8*warp + j;
        int grow = (r >> 5)*HD + b*32 + (r & 31);
        wh[j] = *reinterpret_cast<const float4*>(&whh0[grow*HD + 384 + 4*lane]);
        wx[j] = *reinterpret_cast<const float2*>(&wih0[grow*IIN + 2*lane]);
    }
    float cc = 0.0f, bi = 0.0f, bf = 0.0f, bg = 0.0f, bo = 0.0f;
    if (tid < 32){
        int u = b*32 + tid;
        bi = bih0[u]        + bhh0[u];
        bf = bih0[512 + u]  + bhh0[512 + u];
        bg = bih0[1024 + u] + bhh0[1024 + u];
        bo = bih0[1536 + u] + bhh0[1536 + u];
    }
    __syncthreads();

    for (int t = 0; t < TS; ++t){
        // wait: own-layer h_{t-1} from all 16 blocks
        if (t > 0 && tid < NB0){
            const int* p = &g_flag[0][tid];
            while (ld_acq(p) < t) {}
        }
        __syncthreads();

        float4 vin[4]; float2 vx;
        if (t > 0){
            const float* hp = &g_h[0][t-1][0];
            #pragma unroll
            for (int c = 0; c < 4; c++)
                vin[c] = __ldcg(reinterpret_cast<const float4*>(hp + 128*c + 4*lane));
        } else {
            #pragma unroll
            for (int c = 0; c < 4; c++) vin[c] = make_float4(0,0,0,0);
        }
        vx = *reinterpret_cast<const float2*>(&x[t*IIN + 2*lane]);

        float acc[8];
        #pragma unroll
        for (int j = 0; j < 8; j++){
            const float* wr = WS + (8*warp + j)*384 + 4*lane;
            float a = 0.0f;
            #pragma unroll
            for (int c = 0; c < 3; c++){
                float4 w = *reinterpret_cast<const float4*>(wr + 128*c);
                a = fmaf(w.x, vin[c].x, a); a = fmaf(w.y, vin[c].y, a);
                a = fmaf(w.z, vin[c].z, a); a = fmaf(w.w, vin[c].w, a);
            }
            a = fmaf(wh[j].x, vin[3].x, a); a = fmaf(wh[j].y, vin[3].y, a);
            a = fmaf(wh[j].z, vin[3].z, a); a = fmaf(wh[j].w, vin[3].w, a);
            a = fmaf(wx[j].x, vx.x, a);     a = fmaf(wx[j].y, vx.y, a);
            acc[j] = a;
        }
        #pragma unroll
        for (int j = 0; j < 8; j++){
            #pragma unroll
            for (int off = 16; off; off >>= 1)
                acc[j] += __shfl_xor_sync(0xffffffffu, acc[j], off);
        }
        if (lane < 8){
            float g = acc[0];
            #pragma unroll
            for (int j = 1; j < 8; j++) if (lane == j) g = acc[j];
            sG[8*warp + lane] = g;
        }
        __syncthreads();

        if (tid < 32){
            float iv = sigf (sG[tid]       + bi);
            float fv = sigf (sG[32  + tid] + bf);
            float gv = tanhf(sG[64  + tid] + bg);
            float ov = sigf (sG[96  + tid] + bo);
            cc = fv*cc + iv*gv;
            g_h[0][t][b*32 + tid] = ov * tanhf(cc);
        }
        __syncwarp();
        if (tid == 0) st_rel(&g_flag[0][b], t + 1);
    }
}

// ---------------- layers 1..4 : 32 blocks x 64 rows, K = 512(h^{l-1}) + 512(h^l) ----------------
__device__ void run_l(int layer, int b, int nbPrev,
                      const float* __restrict__ wih, const float* __restrict__ whh,
                      const float* __restrict__ bih, const float* __restrict__ bhh,
                      float* sm)
{
    float* WS = sm;             // [64][768]  cols [0,768)  (512 wih + 256 whh)
    float* sG = sm + 64*768;    // [64]
    const int tid = threadIdx.x, warp = tid >> 5, lane = tid & 31;

    for (int idx = tid; idx < 64*768; idx += NT){
        int r = idx / 768, c = idx - r*768;
        int grow = (r >> 4)*HD + b*16 + (r & 15);
        WS[idx] = (c < 512) ? wih[grow*HD + c] : whh[grow*HD + (c - 512)];
    }
    // Register suffix: cols [768,1024) -> whh cols [256,512)
    float4 w6[4], w7[4];
    #pragma unroll
    for (int j = 0; j < 4; j++){
        int r = 4*warp + j;
        int grow = (r >> 4)*HD + b*16 + (r & 15);
        w6[j] = *reinterpret_cast<const float4*>(&whh[grow*HD + 256 + 4*lane]);
        w7[j] = *reinterpret_cast<const float4*>(&whh[grow*HD + 384 + 4*lane]);
    }
    float cc = 0.0f, bi = 0.0f, bf = 0.0f, bg = 0.0f, bo = 0.0f;
    if (tid < 16){
        int u = b*16 + tid;
        bi = bih[u]        + bhh[u];
        bf = bih[512 + u]  + bhh[512 + u];
        bg = bih[1024 + u] + bhh[1024 + u];
        bo = bih[1536 + u] + bhh[1536 + u];
    }
    __syncthreads();

    for (int t = 0; t < TS; ++t){
        if (tid < nbPrev){
            const int* p = &g_flag[layer-1][tid];
            while (ld_acq(p) <= t) {}
        } else if (tid >= 64 && tid < 96 && t > 0){
            const int* p = &g_flag[layer][tid - 64];
            while (ld_acq(p) < t) {}
        }
        __syncthreads();

        float4 vin[8];
        const float* hl = &g_h[layer-1][t][0];
        #pragma unroll
        for (int c = 0; c < 4; c++)
            vin[c] = __ldcg(reinterpret_cast<const float4*>(hl + 128*c + 4*lane));
        if (t > 0){
            const float* hp = &g_h[layer][t-1][0];
            #pragma unroll
            for (int c = 0; c < 4; c++)
                vin[4+c] = __ldcg(reinterpret_cast<const float4*>(hp + 128*c + 4*lane));
        } else {
            #pragma unroll
            for (int c = 0; c < 4; c++) vin[4+c] = make_float4(0,0,0,0);
        }

        float acc[4];
        #pragma unroll
        for (int j = 0; j < 4; j++){
            const float* wr = WS + (4*warp + j)*768 + 4*lane;
            float a = 0.0f;
            #pragma unroll
            for (int c = 0; c < 6; c++){
                float4 w = *reinterpret_cast<const float4*>(wr + 128*c);
                a = fmaf(w.x, vin[c].x, a); a = fmaf(w.y, vin[c].y, a);
                a = fmaf(w.z, vin[c].z, a); a = fmaf(w.w, vin[c].w, a);
            }
            a = fmaf(w6[j].x, vin[6].x, a); a = fmaf(w6[j].y, vin[6].y, a);
            a = fmaf(w6[j].z, vin[6].z, a); a = fmaf(w6[j].w, vin[6].w, a);
            a = fmaf(w7[j].x, vin[7].x, a); a = fmaf(w7[j].y, vin[7].y, a);
            a = fmaf(w7[j].z, vin[7].z, a); a = fmaf(w7[j].w, vin[7].w, a);
            acc[j] = a;
        }
        #pragma unroll
        for (int j = 0; j < 4; j++){
            #pragma unroll
            for (int off = 16; off; off >>= 1)
                acc[j] += __shfl_xor_sync(0xffffffffu, acc[j], off);
        }
        if (lane < 4){
            float g = acc[0];
            #pragma unroll
            for (int j = 1; j < 4; j++) if (lane == j) g = acc[j];
            sG[4*warp + lane] = g;
        }
        __syncthreads();

        if (tid < 16){
            float iv = sigf (sG[tid]      + bi);
            float fv = sigf (sG[16 + tid] + bf);
            float gv = tanhf(sG[32 + tid] + bg);
            float ov = sigf (sG[48 + tid] + bo);
            cc = fv*cc + iv*gv;
            g_h[layer][t][b*16 + tid] = ov * tanhf(cc);
        }
        __syncwarp();
        if (tid == 0) st_rel(&g_flag[layer][b], t + 1);
    }
}

__global__ void __launch_bounds__(NT, 1) lstm_kernel(
    const float* __restrict__ x,
    const float* __restrict__ w_ih0, const float* __restrict__ w_hh0,
    const float* __restrict__ b_ih0, const float* __restrict__ b_hh0,
    const float* __restrict__ w_ih,  const float* __restrict__ w_hh,
    const float* __restrict__ b_ih,  const float* __restrict__ b_hh)
{
    extern __shared__ float sm[];
    int bid = blockIdx.x;
    if (bid < NB0){
        run_l0(bid, x, w_ih0, w_hh0, b_ih0, b_hh0, sm);
    } else {
        int r = bid - NB0;
        int layer = 1 + (r >> 5);
        int b = r & 31;
        size_t off = (size_t)(layer - 1) * (4*HD);
        run_l(layer, b, (layer == 1) ? NB0 : NB1,
              w_ih + off*HD, w_hh + off*HD, b_ih + off, b_hh + off, sm);
    }
}

// ---------------- epilogue: attention pooling ----------------

__global__ void k_zero(){
    int i = blockIdx.x*blockDim.x + threadIdx.x;
    if (i < NL*64) (&g_flag[0][0])[i] = 0;
}

__global__ void k_e(const float* __restrict__ wlin, const float* __restrict__ blin){
    int t = blockIdx.x;
    int tid = threadIdx.x;
    float a = 0.0f;
    for (int j = tid; j < HD; j += 128) a += g_h[NL-1][t][j] * wlin[j];
    #pragma unroll
    for (int off = 16; off; off >>= 1) a += __shfl_xor_sync(0xffffffffu, a, off);
    __shared__ float sr[4];
    if ((tid & 31) == 0) sr[tid >> 5] = a;
    __syncthreads();
    if (tid == 0) g_z[t] = tanhf(sr[0] + sr[1] + sr[2] + sr[3] + blin[0]);
}

__global__ void k_softmax(){
    int tid = threadIdx.x;
    __shared__ float sr[32];
    __shared__ float sbc;
    float z1 = g_z[tid], z2 = g_z[tid + 1024];
    float m = fmaxf(z1, z2);
    #pragma unroll
    for (int off = 16; off; off >>= 1) m = fmaxf(m, __shfl_xor_sync(0xffffffffu, m, off));
    if ((tid & 31) == 0) sr[tid >> 5] = m;
    __syncthreads();
    if (tid < 32){
        float v = sr[tid];
        #pragma unroll
        for (int off = 16; off; off >>= 1) v = fmaxf(v, __shfl_xor_sync(0xffffffffu, v, off));
        if (tid == 0) sbc = v;
    }
    __syncthreads();
    float mm = sbc;
    float e1 = expf(z1 - mm), e2 = expf(z2 - mm);
    float s = e1 + e2;
    #pragma unroll
    for (int off = 16; off; off >>= 1) s += __shfl_xor_sync(0xffffffffu, s, off);
    __syncthreads();
    if ((tid & 31) == 0) sr[tid >> 5] = s;
    __syncthreads();
    if (tid < 32){
        float v = sr[tid];
        #pragma unroll
        for (int off = 16; off; off >>= 1) v += __shfl_xor_sync(0xffffffffu, v, off);
        if (tid == 0) sbc = v;
    }
    __syncthreads();
    float inv = 1.0f / (sbc * (float)TS);
    g_wt[tid]        = e1 * inv;
    g_wt[tid + 1024] = e2 * inv;
}

__global__ void k_part(){
    int bb = blockIdx.x, tid = threadIdx.x;
    float a = 0.0f;
    int t0 = bb * 64;
    #pragma unroll 4
    for (int t = t0; t < t0 + 64; ++t) a += g_wt[t] * g_h[NL-1][t][tid];
    g_part[bb][tid] = a;
}

__global__ void k_final(float* __restrict__ out){
    int tid = threadIdx.x;
    float a = 0.0f;
    #pragma unroll
    for (int bb = 0; bb < 32; ++bb) a += g_part[bb][tid];
    out[tid] = a;
}

extern "C" void kernel_launch(void* const* d_in, const int* in_sizes, int n_in,
                              void* d_out, int out_size)
{
    const float* x     = (const float*)d_in[0];
    const float* w_ih0 = (const float*)d_in[1];
    const float* w_hh0 = (const float*)d_in[2];
    const float* b_ih0 = (const float*)d_in[3];
    const float* b_hh0 = (const float*)d_in[4];
    const float* w_ih  = (const float*)d_in[5];
    const float* w_hh  = (const float*)d_in[6];
    const float* b_ih  = (const float*)d_in[7];
    const float* b_hh  = (const float*)d_in[8];
    const float* w_lin = (const float*)d_in[9];
    const float* b_lin = (const float*)d_in[10];

    cudaFuncSetAttribute(lstm_kernel, cudaFuncAttributeMaxDynamicSharedMemorySize, SMEM_BYTES);

    k_zero<<<2, 256>>>();
    lstm_kernel<<<TOTAL_BLOCKS, NT, SMEM_BYTES>>>(x, w_ih0, w_hh0, b_ih0, b_hh0,
                                                  w_ih, w_hh, b_ih, b_hh);
    k_e<<<TS, 128>>>(w_lin, b_lin);
    k_softmax<<<1, 1024>>>();
    k_part<<<32, 512>>>();
    k_final<<<1, 512>>>((float*)d_out);
}

// round 4
// speedup vs baseline: 1.3600x; 1.1904x over previous
#include <cuda_runtime.h>
#include <math.h>

// Problem constants
#define TS   2048
#define IIN  64
#define HD   512
#define NL   5

// Partitioning
#define NB0  16      // layer 0: 16 blocks x 128 rows
#define NB1  32      // layers 1..4: 32 blocks x 64 rows
#define NT   512
#define TOTAL_BLOCKS (NB0 + 4*NB1)   // 144 blocks, 1/SM, co-resident

// Dynamic SMEM (floats):
//  layer0 : 128*384 (whh cols 0..383) + 128 sG + 128 sB + 256 zx  = 49664
//  layer1+: 64*512 (wih) + 64*256 (whh cols 0..255) + 64 + 64 + 128 = 49408
#define SMEM_BYTES (49664*4)

// Device scratch
__device__ float g_h[NL][TS][HD];
__device__ int   g_cnt[NL][TS];      // per (layer, t) completion counters
__device__ float g_z[TS];
__device__ float g_wt[TS];
__device__ float g_part[32][HD];
__device__ int   g_dummy;

__device__ __forceinline__ float sigf(float v){ return 1.0f/(1.0f + expf(-v)); }

__device__ __forceinline__ int ld_acq(const int* p){
    int v; asm volatile("ld.global.acquire.gpu.b32 %0, [%1];" : "=r"(v) : "l"(p) : "memory");
    return v;
}

// ---------------- layer 0 : 16 blocks x 128 rows ----------------
// Critical: W_hh (512 cols: 384 SMEM + 128 regs). x-part precomputed into zx ring.
__device__ void run_l0(int b, const float* __restrict__ x,
                       const float* __restrict__ wih0, const float* __restrict__ whh0,
                       const float* __restrict__ bih0, const float* __restrict__ bhh0,
                       float* sm)
{
    float* WS = sm;               // [128][384]
    float* sG = sm + 128*384;     // [128]
    float* sB = sG + 128;         // [128]
    float* zx = sB + 128;         // [2][128]
    const int tid = threadIdx.x, warp = tid >> 5, lane = tid & 31;

    for (int idx = tid; idx < 128*384; idx += NT){
        int r = idx / 384, c = idx - r*384;
        int grow = (r >> 5)*HD + b*32 + (r & 31);
        WS[idx] = whh0[grow*HD + c];
    }
    float4 wh[8]; float2 wx[8];
    #pragma unroll
    for (int j = 0; j < 8; j++){
        int r = 8*warp + j;
        int grow = (r >> 5)*HD + b*32 + (r & 31);
        wh[j] = *reinterpret_cast<const float4*>(&whh0[grow*HD + 384 + 4*lane]);
        wx[j] = *reinterpret_cast<const float2*>(&wih0[grow*IIN + 2*lane]);
    }
    if (tid < 128){
        int grow = (tid >> 5)*HD + b*32 + (tid & 31);
        sB[tid] = bih0[grow] + bhh0[grow];
    }
    float cc = 0.0f;
    __syncthreads();

    // prologue: zx[0] = W_ih0 . x_0 + bias
    {
        float2 vx = *reinterpret_cast<const float2*>(&x[2*lane]);
        float acc[8];
        #pragma unroll
        for (int j = 0; j < 8; j++){
            float a = wx[j].x * vx.x; a = fmaf(wx[j].y, vx.y, a);
            #pragma unroll
            for (int off = 16; off; off >>= 1) a += __shfl_xor_sync(~0u, a, off);
            acc[j] = a;
        }
        if (lane < 8){
            float g = acc[0];
            #pragma unroll
            for (int j = 1; j < 8; j++) if (lane == j) g = acc[j];
            zx[8*warp + lane] = g + sB[8*warp + lane];
        }
    }

    for (int t = 0; t < TS; ++t){
        if (t > 0){
            if (tid == 0){ const int* p = &g_cnt[0][t-1]; while (ld_acq(p) < NB0) {} }
            __syncthreads();
        }
        float4 vin[4];
        if (t > 0){
            const float* hp = &g_h[0][t-1][0];
            #pragma unroll
            for (int c = 0; c < 4; c++)
                vin[c] = __ldcg(reinterpret_cast<const float4*>(hp + 128*c + 4*lane));
        } else {
            #pragma unroll
            for (int c = 0; c < 4; c++) vin[c] = make_float4(0,0,0,0);
        }
        float acc[8];
        #pragma unroll
        for (int j = 0; j < 8; j++){
            const float* wr = WS + (8*warp + j)*384 + 4*lane;
            float a = 0.0f;
            #pragma unroll
            for (int c = 0; c < 3; c++){
                float4 w = *reinterpret_cast<const float4*>(wr + 128*c);
                a = fmaf(w.x, vin[c].x, a); a = fmaf(w.y, vin[c].y, a);
                a = fmaf(w.z, vin[c].z, a); a = fmaf(w.w, vin[c].w, a);
            }
            a = fmaf(wh[j].x, vin[3].x, a); a = fmaf(wh[j].y, vin[3].y, a);
            a = fmaf(wh[j].z, vin[3].z, a); a = fmaf(wh[j].w, vin[3].w, a);
            acc[j] = a;
        }
        #pragma unroll
        for (int j = 0; j < 8; j++){
            #pragma unroll
            for (int off = 16; off; off >>= 1)
                acc[j] += __shfl_xor_sync(~0u, acc[j], off);
        }
        if (lane < 8){
            float g = acc[0];
            #pragma unroll
            for (int j = 1; j < 8; j++) if (lane == j) g = acc[j];
            sG[8*warp + lane] = g;
        }
        __syncthreads();

        if (tid < 32){
            const float* zz = zx + (t & 1)*128;
            float iv = sigf (sG[tid]      + zz[tid]);
            float fv = sigf (sG[32 + tid] + zz[32 + tid]);
            float gv = tanhf(sG[64 + tid] + zz[64 + tid]);
            float ov = sigf (sG[96 + tid] + zz[96 + tid]);
            cc = fv*cc + iv*gv;
            g_h[0][t][b*32 + tid] = ov * tanhf(cc);
        }
        __syncwarp();
        if (tid == 0){ __threadfence(); atomicAdd(&g_cnt[0][t], 1); }

        // phase E: precompute zx for t+1 (x always available)
        if (t + 1 < TS){
            float2 vx = *reinterpret_cast<const float2*>(&x[(t+1)*IIN + 2*lane]);
            float a2[8];
            #pragma unroll
            for (int j = 0; j < 8; j++){
                float a = wx[j].x * vx.x; a = fmaf(wx[j].y, vx.y, a);
                #pragma unroll
                for (int off = 16; off; off >>= 1) a += __shfl_xor_sync(~0u, a, off);
                a2[j] = a;
            }
            if (lane < 8){
                float g = a2[0];
                #pragma unroll
                for (int j = 1; j < 8; j++) if (lane == j) g = a2[j];
                zx[((t+1) & 1)*128 + 8*warp + lane] = g + sB[8*warp + lane];
            }
        }
    }
}

// ---------------- layers 1..4 : 32 blocks x 64 rows ----------------
// Critical: W_hh (512 cols: 256 SMEM + 256 regs). W_ih part precomputed into zr ring
// one step ahead (enforces a standing 2-step lag behind the previous layer).
__device__ void run_l(int layer, int b, int nbPrev,
                      const float* __restrict__ wih, const float* __restrict__ whh,
                      const float* __restrict__ bih, const float* __restrict__ bhh,
                      float* sm)
{
    float* WI = sm;              // [64][512]
    float* WH = sm + 64*512;     // [64][256]
    float* sG = WH + 64*256;     // [64]
    float* sB = sG + 64;         // [64]
    float* zr = sB + 64;         // [2][64]
    const int tid = threadIdx.x, warp = tid >> 5, lane = tid & 31;

    for (int idx = tid; idx < 64*512; idx += NT){
        int r = idx >> 9, c = idx & 511;
        int grow = (r >> 4)*HD + b*16 + (r & 15);
        WI[idx] = wih[grow*HD + c];
    }
    for (int idx = tid; idx < 64*256; idx += NT){
        int r = idx >> 8, c = idx & 255;
        int grow = (r >> 4)*HD + b*16 + (r & 15);
        WH[idx] = whh[grow*HD + c];
    }
    float4 w2[4], w3[4];
    #pragma unroll
    for (int j = 0; j < 4; j++){
        int r = 4*warp + j;
        int grow = (r >> 4)*HD + b*16 + (r & 15);
        w2[j] = *reinterpret_cast<const float4*>(&whh[grow*HD + 256 + 4*lane]);
        w3[j] = *reinterpret_cast<const float4*>(&whh[grow*HD + 384 + 4*lane]);
    }
    if (tid < 64){
        int grow = (tid >> 4)*HD + b*16 + (tid & 15);
        sB[tid] = bih[grow] + bhh[grow];
    }
    float cc = 0.0f;
    __syncthreads();

    // prologue: zr[0] = W_ih . h^{l-1}_0 + bias
    {
        if (tid == 0){ const int* p = &g_cnt[layer-1][0]; while (ld_acq(p) < nbPrev) {} }
        __syncthreads();
        const float* hp = &g_h[layer-1][0][0];
        float4 pv[4];
        #pragma unroll
        for (int c = 0; c < 4; c++)
            pv[c] = __ldcg(reinterpret_cast<const float4*>(hp + 128*c + 4*lane));
        float acc[4];
        #pragma unroll
        for (int j = 0; j < 4; j++){
            const float* wr = WI + (4*warp + j)*512 + 4*lane;
            float a = 0.0f;
            #pragma unroll
            for (int c = 0; c < 4; c++){
                float4 w = *reinterpret_cast<const float4*>(wr + 128*c);
                a = fmaf(w.x, pv[c].x, a); a = fmaf(w.y, pv[c].y, a);
                a = fmaf(w.z, pv[c].z, a); a = fmaf(w.w, pv[c].w, a);
            }
            #pragma unroll
            for (int off = 16; off; off >>= 1) a += __shfl_xor_sync(~0u, a, off);
            acc[j] = a;
        }
        if (lane < 4){
            float g = acc[0];
            #pragma unroll
            for (int j = 1; j < 4; j++) if (lane == j) g = acc[j];
            zr[4*warp + lane] = g + sB[4*warp + lane];
        }
    }

    for (int t = 0; t < TS; ++t){
        // critical wait: own-layer h_{t-1}
        if (t > 0){
            if (tid == 0){ const int* p = &g_cnt[layer][t-1]; while (ld_acq(p) < NB1) {} }
            __syncthreads();
        }
        float4 vin[4];
        if (t > 0){
            const float* hp = &g_h[layer][t-1][0];
            #pragma unroll
            for (int c = 0; c < 4; c++)
                vin[c] = __ldcg(reinterpret_cast<const float4*>(hp + 128*c + 4*lane));
        } else {
            #pragma unroll
            for (int c = 0; c < 4; c++) vin[c] = make_float4(0,0,0,0);
        }
        float acc[4];
        #pragma unroll
        for (int j = 0; j < 4; j++){
            const float* wr = WH + (4*warp + j)*256 + 4*lane;
            float a = 0.0f;
            float4 w = *reinterpret_cast<const float4*>(wr);
            a = fmaf(w.x, vin[0].x, a); a = fmaf(w.y, vin[0].y, a);
            a = fmaf(w.z, vin[0].z, a); a = fmaf(w.w, vin[0].w, a);
            float4 u = *reinterpret_cast<const float4*>(wr + 128);
            a = fmaf(u.x, vin[1].x, a); a = fmaf(u.y, vin[1].y, a);
            a = fmaf(u.z, vin[1].z, a); a = fmaf(u.w, vin[1].w, a);
            a = fmaf(w2[j].x, vin[2].x, a); a = fmaf(w2[j].y, vin[2].y, a);
            a = fmaf(w2[j].z, vin[2].z, a); a = fmaf(w2[j].w, vin[2].w, a);
            a = fmaf(w3[j].x, vin[3].x, a); a = fmaf(w3[j].y, vin[3].y, a);
            a = fmaf(w3[j].z, vin[3].z, a); a = fmaf(w3[j].w, vin[3].w, a);
            acc[j] = a;
        }
        #pragma unroll
        for (int j = 0; j < 4; j++){
            #pragma unroll
            for (int off = 16; off; off >>= 1)
                acc[j] += __shfl_xor_sync(~0u, acc[j], off);
        }
        if (lane < 4){
            float g = acc[0];
            #pragma unroll
            for (int j = 1; j < 4; j++) if (lane == j) g = acc[j];
            sG[4*warp + lane] = g;
        }
        __syncthreads();

        if (tid < 16){
            const float* zz = zr + (t & 1)*64;
            float iv = sigf (sG[tid]      + zz[tid]);
            float fv = sigf (sG[16 + tid] + zz[16 + tid]);
            float gv = tanhf(sG[32 + tid] + zz[32 + tid]);
            float ov = sigf (sG[48 + tid] + zz[48 + tid]);
            cc = fv*cc + iv*gv;
            g_h[layer][t][b*16 + tid] = ov * tanhf(cc);
        }
        __syncwarp();
        if (tid == 0){ __threadfence(); atomicAdd(&g_cnt[layer][t], 1); }

        // phase E: precompute zr for step t+1 from h^{l-1}_{t+1}
        if (t + 1 < TS){
            if (tid == 0){ const int* p = &g_cnt[layer-1][t+1]; while (ld_acq(p) < nbPrev) {} }
            __syncthreads();
            const float* hp = &g_h[layer-1][t+1][0];
            float4 pv[4];
            #pragma unroll
            for (int c = 0; c < 4; c++)
                pv[c] = __ldcg(reinterpret_cast<const float4*>(hp + 128*c + 4*lane));
            float a2[4];
            #pragma unroll
            for (int j = 0; j < 4; j++){
                const float* wr = WI + (4*warp + j)*512 + 4*lane;
                float a = 0.0f;
                #pragma unroll
                for (int c = 0; c < 4; c++){
                    float4 w = *reinterpret_cast<const float4*>(wr + 128*c);
                    a = fmaf(w.x, pv[c].x, a); a = fmaf(w.y, pv[c].y, a);
                    a = fmaf(w.z, pv[c].z, a); a = fmaf(w.w, pv[c].w, a);
                }
                #pragma unroll
                for (int off = 16; off; off >>= 1) a += __shfl_xor_sync(~0u, a, off);
                a2[j] = a;
            }
            if (lane < 4){
                float g = a2[0];
                #pragma unroll
                for (int j = 1; j < 4; j++) if (lane == j) g = a2[j];
                zr[((t+1) & 1)*64 + 4*warp + lane] = g + sB[4*warp + lane];
            }
        }
    }
}

__global__ void __launch_bounds__(NT, 1) lstm_kernel(
    const float* __restrict__ x,
    const float* __restrict__ w_ih0, const float* __restrict__ w_hh0,
    const float* __restrict__ b_ih0, const float* __restrict__ b_hh0,
    const float* __restrict__ w_ih,  const float* __restrict__ w_hh,
    const float* __restrict__ b_ih,  const float* __restrict__ b_hh)
{
    extern __shared__ float sm[];
    int bid = blockIdx.x;
    if (bid < NB0){
        run_l0(bid, x, w_ih0, w_hh0, b_ih0, b_hh0, sm);
    } else {
        int r = bid - NB0;
        int layer = 1 + (r >> 5);
        int b = r & 31;
        size_t off = (size_t)(layer - 1) * (4*HD);
        run_l(layer, b, (layer == 1) ? NB0 : NB1,
              w_ih + off*HD, w_hh + off*HD, b_ih + off, b_hh + off, sm);
    }
}

// ---------------- epilogue + helpers ----------------

__global__ void k_zero(){
    int i = blockIdx.x*blockDim.x + threadIdx.x;
    if (i < NL*TS) (&g_cnt[0][0])[i] = 0;
}

__global__ void k_dummy(){ if (threadIdx.x == 0) g_dummy = blockIdx.x; }

__global__ void k_e(const float* __restrict__ wlin, const float* __restrict__ blin){
    int t = blockIdx.x;
    int tid = threadIdx.x;
    float a = 0.0f;
    for (int j = tid; j < HD; j += 128) a += g_h[NL-1][t][j] * wlin[j];
    #pragma unroll
    for (int off = 16; off; off >>= 1) a += __shfl_xor_sync(~0u, a, off);
    __shared__ float sr[4];
    if ((tid & 31) == 0) sr[tid >> 5] = a;
    __syncthreads();
    if (tid == 0) g_z[t] = tanhf(sr[0] + sr[1] + sr[2] + sr[3] + blin[0]);
}

__global__ void k_softmax(){
    int tid = threadIdx.x;
    __shared__ float sr[32];
    __shared__ float sbc;
    float z1 = g_z[tid], z2 = g_z[tid + 1024];
    float m = fmaxf(z1, z2);
    #pragma unroll
    for (int off = 16; off; off >>= 1) m = fmaxf(m, __shfl_xor_sync(~0u, m, off));
    if ((tid & 31) == 0) sr[tid >> 5] = m;
    __syncthreads();
    if (tid < 32){
        float v = sr[tid];
        #pragma unroll
        for (int off = 16; off; off >>= 1) v = fmaxf(v, __shfl_xor_sync(~0u, v, off));
        if (tid == 0) sbc = v;
    }
    __syncthreads();
    float mm = sbc;
    float e1 = expf(z1 - mm), e2 = expf(z2 - mm);
    float s = e1 + e2;
    #pragma unroll
    for (int off = 16; off; off >>= 1) s += __shfl_xor_sync(~0u, s, off);
    __syncthreads();
    if ((tid & 31) == 0) sr[tid >> 5] = s;
    __syncthreads();
    if (tid < 32){
        float v = sr[tid];
        #pragma unroll
        for (int off = 16; off; off >>= 1) v += __shfl_xor_sync(~0u, v, off);
        if (tid == 0) sbc = v;
    }
    __syncthreads();
    float inv = 1.0f / (sbc * (float)TS);
    g_wt[tid]        = e1 * inv;
    g_wt[tid + 1024] = e2 * inv;
}

__global__ void k_part(){
    int bb = blockIdx.x, tid = threadIdx.x;
    float a = 0.0f;
    int t0 = bb * 64;
    #pragma unroll 4
    for (int t = t0; t < t0 + 64; ++t) a += g_wt[t] * g_h[NL-1][t][tid];
    g_part[bb][tid] = a;
}

__global__ void k_final(float* __restrict__ out){
    int tid = threadIdx.x;
    float a = 0.0f;
    #pragma unroll
    for (int bb = 0; bb < 32; ++bb) a += g_part[bb][tid];
    out[tid] = a;
}

extern "C" void kernel_launch(void* const* d_in, const int* in_sizes, int n_in,
                              void* d_out, int out_size)
{
    const float* x     = (const float*)d_in[0];
    const float* w_ih0 = (const float*)d_in[1];
    const float* w_hh0 = (const float*)d_in[2];
    const float* b_ih0 = (const float*)d_in[3];
    const float* b_hh0 = (const float*)d_in[4];
    const float* w_ih  = (const float*)d_in[5];
    const float* w_hh  = (const float*)d_in[6];
    const float* b_ih  = (const float*)d_in[7];
    const float* b_hh  = (const float*)d_in[8];
    const float* w_lin = (const float*)d_in[9];
    const float* b_lin = (const float*)d_in[10];

    cudaFuncSetAttribute(lstm_kernel, cudaFuncAttributeMaxDynamicSharedMemorySize, SMEM_BYTES);

    k_zero<<<(NL*TS + 255)/256, 256>>>();
    k_dummy<<<1, 32>>>();               // position lstm_kernel as the 4th launch
    k_dummy<<<1, 32>>>();               // so ncu's fixed capture window hits it
    lstm_kernel<<<TOTAL_BLOCKS, NT, SMEM_BYTES>>>(x, w_ih0, w_hh0, b_ih0, b_hh0,
                                                  w_ih, w_hh, b_ih, b_hh);
    k_e<<<TS, 128>>>(w_lin, b_lin);
    k_softmax<<<1, 1024>>>();
    k_part<<<32, 512>>>();
    k_final<<<1, 512>>>((float*)d_out);
}

// round 5
// speedup vs baseline: 1.7712x; 1.3024x over previous
#include <cuda_runtime.h>
#include <math.h>

// Problem constants
#define TS   2048
#define IIN  64
#define HD   512
#define NL   5

// Partitioning
#define NB0  16      // layer 0: 16 blocks x 128 rows
#define NB1  32      // layers 1..4: 32 blocks x 64 rows
#define NT   512
#define TOTAL_BLOCKS (NB0 + 4*NB1)   // 144 blocks, 1/SM, co-resident

// Dynamic SMEM (floats):
//  layer0 : 128*256 + 128 sG + 128 sB + 256 zx = 33280
//  layer1+: 64*512  + 64  sG + 64  sB + 128 zr = 33024
#define SMEM_BYTES (33280*4)

// Device scratch
__device__ float g_h[NL][TS][HD];
__device__ int   g_flag[NL][32][32];   // one 128B line per (layer, producer block)
__device__ float g_z[TS];
__device__ float g_wt[TS];
__device__ float g_part[32][HD];
__device__ int   g_dummy;

__device__ __forceinline__ float sigf(float v){ return 1.0f/(1.0f + __expf(-v)); }

__device__ __forceinline__ int ld_acq(const int* p){
    int v; asm volatile("ld.global.acquire.gpu.b32 %0, [%1];" : "=r"(v) : "l"(p) : "memory");
    return v;
}
__device__ __forceinline__ void st_rel(int* p, int v){
    asm volatile("st.global.release.gpu.b32 [%0], %1;" :: "l"(p), "r"(v) : "memory");
}

// ---------------- layer 0 : 16 blocks x 128 rows ----------------
// hh: cols [0,256) in SMEM, cols [256,512) in registers. x-part in zx ring.
__device__ void run_l0(int b, const float* __restrict__ x,
                       const float* __restrict__ wih0, const float* __restrict__ whh0,
                       const float* __restrict__ bih0, const float* __restrict__ bhh0,
                       float* sm)
{
    float* WS = sm;               // [128][256]
    float* sG = sm + 128*256;     // [128]
    float* sB = sG + 128;         // [128]
    float* zx = sB + 128;         // [2][128]
    const int tid = threadIdx.x, warp = tid >> 5, lane = tid & 31;

    for (int idx = tid; idx < 128*256; idx += NT){
        int r = idx >> 8, c = idx & 255;
        int grow = (r >> 5)*HD + b*32 + (r & 31);
        WS[idx] = whh0[grow*HD + c];
    }
    float4 wh[8][2]; float2 wx[8];
    #pragma unroll
    for (int j = 0; j < 8; j++){
        int r = 8*warp + j;
        int grow = (r >> 5)*HD + b*32 + (r & 31);
        wh[j][0] = *reinterpret_cast<const float4*>(&whh0[grow*HD + 256 + 4*lane]);
        wh[j][1] = *reinterpret_cast<const float4*>(&whh0[grow*HD + 384 + 4*lane]);
        wx[j]    = *reinterpret_cast<const float2*>(&wih0[grow*IIN + 2*lane]);
    }
    if (tid < 128){
        int grow = (tid >> 5)*HD + b*32 + (tid & 31);
        sB[tid] = bih0[grow] + bhh0[grow];
    }
    float cc = 0.0f;
    __syncthreads();

    // prologue: zx[0] = W_ih0 . x_0 + bias
    {
        float2 vx = *reinterpret_cast<const float2*>(&x[2*lane]);
        float acc[8];
        #pragma unroll
        for (int j = 0; j < 8; j++){
            float a = wx[j].x * vx.x; a = fmaf(wx[j].y, vx.y, a);
            #pragma unroll
            for (int off = 16; off; off >>= 1) a += __shfl_xor_sync(~0u, a, off);
            acc[j] = a;
        }
        if (lane < 8){
            float g = acc[0];
            #pragma unroll
            for (int j = 1; j < 8; j++) if (lane == j) g = acc[j];
            zx[8*warp + lane] = g + sB[8*warp + lane];
        }
    }

    for (int t = 0; t < TS; ++t){
        if (t > 0 && tid < NB0){
            const int* p = &g_flag[0][tid][0];
            while (ld_acq(p) < t) {}
        }
        __syncthreads();

        float4 vin[4];
        if (t > 0){
            const float* hp = &g_h[0][t-1][0];
            #pragma unroll
            for (int c = 0; c < 4; c++)
                vin[c] = __ldcg(reinterpret_cast<const float4*>(hp + 128*c + 4*lane));
        } else {
            #pragma unroll
            for (int c = 0; c < 4; c++) vin[c] = make_float4(0,0,0,0);
        }

        float acc[8];
        #pragma unroll
        for (int j = 0; j < 8; j++){
            const float* wr = WS + (8*warp + j)*256 + 4*lane;
            float a = 0.0f;
            float4 w0 = *reinterpret_cast<const float4*>(wr);
            a = fmaf(w0.x, vin[0].x, a); a = fmaf(w0.y, vin[0].y, a);
            a = fmaf(w0.z, vin[0].z, a); a = fmaf(w0.w, vin[0].w, a);
            float4 w1 = *reinterpret_cast<const float4*>(wr + 128);
            a = fmaf(w1.x, vin[1].x, a); a = fmaf(w1.y, vin[1].y, a);
            a = fmaf(w1.z, vin[1].z, a); a = fmaf(w1.w, vin[1].w, a);
            a = fmaf(wh[j][0].x, vin[2].x, a); a = fmaf(wh[j][0].y, vin[2].y, a);
            a = fmaf(wh[j][0].z, vin[2].z, a); a = fmaf(wh[j][0].w, vin[2].w, a);
            a = fmaf(wh[j][1].x, vin[3].x, a); a = fmaf(wh[j][1].y, vin[3].y, a);
            a = fmaf(wh[j][1].z, vin[3].z, a); a = fmaf(wh[j][1].w, vin[3].w, a);
            acc[j] = a;
        }
        #pragma unroll
        for (int j = 0; j < 8; j++){
            #pragma unroll
            for (int off = 16; off; off >>= 1)
                acc[j] += __shfl_xor_sync(~0u, acc[j], off);
        }
        if (lane < 8){
            float g = acc[0];
            #pragma unroll
            for (int j = 1; j < 8; j++) if (lane == j) g = acc[j];
            sG[8*warp + lane] = g;
        }
        __syncthreads();

        if (tid < 32){
            const float* zz = zx + (t & 1)*128;
            float iv = sigf (sG[tid]      + zz[tid]);
            float fv = sigf (sG[32 + tid] + zz[32 + tid]);
            float gv = tanhf(sG[64 + tid] + zz[64 + tid]);
            float ov = sigf (sG[96 + tid] + zz[96 + tid]);
            cc = fv*cc + iv*gv;
            g_h[0][t][b*32 + tid] = ov * tanhf(cc);
        }
        if (warp == 0){
            __syncwarp();
            if (lane == 0) st_rel(&g_flag[0][b][0], t + 1);
        }

        // phase E: zx for t+1 (x always available)
        if (t + 1 < TS){
            float2 vx = *reinterpret_cast<const float2*>(&x[(t+1)*IIN + 2*lane]);
            float a2[8];
            #pragma unroll
            for (int j = 0; j < 8; j++){
                float a = wx[j].x * vx.x; a = fmaf(wx[j].y, vx.y, a);
                #pragma unroll
                for (int off = 16; off; off >>= 1) a += __shfl_xor_sync(~0u, a, off);
                a2[j] = a;
            }
            if (lane < 8){
                float g = a2[0];
                #pragma unroll
                for (int j = 1; j < 8; j++) if (lane == j) g = a2[j];
                zx[((t+1) & 1)*128 + 8*warp + lane] = g + sB[8*warp + lane];
            }
        }
    }
}

// ---------------- layers 1..4 : 32 blocks x 64 rows ----------------
// hh fully register-resident (zero LDS on critical path). ih precomputed
// one step ahead from SMEM into the zr ring.
__device__ void run_l(int layer, int b, int nbPrev,
                      const float* __restrict__ wih, const float* __restrict__ whh,
                      const float* __restrict__ bih, const float* __restrict__ bhh,
                      float* sm)
{
    float* WI = sm;              // [64][512]
    float* sG = sm + 64*512;     // [64]
    float* sB = sG + 64;         // [64]
    float* zr = sB + 64;         // [2][64]
    const int tid = threadIdx.x, warp = tid >> 5, lane = tid & 31;

    for (int idx = tid; idx < 64*512; idx += NT){
        int r = idx >> 9, c = idx & 511;
        int grow = (r >> 4)*HD + b*16 + (r & 15);
        WI[idx] = wih[grow*HD + c];
    }
    float4 wh[4][4];
    #pragma unroll
    for (int j = 0; j < 4; j++){
        int r = 4*warp + j;
        int grow = (r >> 4)*HD + b*16 + (r & 15);
        #pragma unroll
        for (int c = 0; c < 4; c++)
            wh[j][c] = *reinterpret_cast<const float4*>(&whh[grow*HD + 128*c + 4*lane]);
    }
    if (tid < 64){
        int grow = (tid >> 4)*HD + b*16 + (tid & 15);
        sB[tid] = bih[grow] + bhh[grow];
    }
    float cc = 0.0f;
    __syncthreads();

    // prologue: zr[0] = W_ih . h^{l-1}_0 + bias
    {
        if (tid < nbPrev){
            const int* p = &g_flag[layer-1][tid][0];
            while (ld_acq(p) < 1) {}
        }
        __syncthreads();
        const float* hp = &g_h[layer-1][0][0];
        float4 pv[4];
        #pragma unroll
        for (int c = 0; c < 4; c++)
            pv[c] = __ldcg(reinterpret_cast<const float4*>(hp + 128*c + 4*lane));
        float acc[4];
        #pragma unroll
        for (int j = 0; j < 4; j++){
            const float* wr = WI + (4*warp + j)*512 + 4*lane;
            float a = 0.0f;
            #pragma unroll
            for (int c = 0; c < 4; c++){
                float4 w = *reinterpret_cast<const float4*>(wr + 128*c);
                a = fmaf(w.x, pv[c].x, a); a = fmaf(w.y, pv[c].y, a);
                a = fmaf(w.z, pv[c].z, a); a = fmaf(w.w, pv[c].w, a);
            }
            #pragma unroll
            for (int off = 16; off; off >>= 1) a += __shfl_xor_sync(~0u, a, off);
            acc[j] = a;
        }
        if (lane < 4){
            float g = acc[0];
            #pragma unroll
            for (int j = 1; j < 4; j++) if (lane == j) g = acc[j];
            zr[4*warp + lane] = g + sB[4*warp + lane];
        }
    }

    for (int t = 0; t < TS; ++t){
        // parallel polls: warp0 -> own layer t-1 ; warp1 -> prev layer t+1
        if (t > 0 && tid < NB1){
            const int* p = &g_flag[layer][tid][0];
            while (ld_acq(p) < t) {}
        } else if (t + 1 < TS && tid >= 32 && tid < 32 + nbPrev){
            const int* p = &g_flag[layer-1][tid-32][0];
            while (ld_acq(p) < t + 2) {}
        }
        __syncthreads();

        float4 vin[4];
        if (t > 0){
            const float* hp = &g_h[layer][t-1][0];
            #pragma unroll
            for (int c = 0; c < 4; c++)
                vin[c] = __ldcg(reinterpret_cast<const float4*>(hp + 128*c + 4*lane));
        } else {
            #pragma unroll
            for (int c = 0; c < 4; c++) vin[c] = make_float4(0,0,0,0);
        }

        float acc[4];
        #pragma unroll
        for (int j = 0; j < 4; j++){
            float a = 0.0f;
            #pragma unroll
            for (int c = 0; c < 4; c++){
                a = fmaf(wh[j][c].x, vin[c].x, a); a = fmaf(wh[j][c].y, vin[c].y, a);
                a = fmaf(wh[j][c].z, vin[c].z, a); a = fmaf(wh[j][c].w, vin[c].w, a);
            }
            acc[j] = a;
        }
        #pragma unroll
        for (int j = 0; j < 4; j++){
            #pragma unroll
            for (int off = 16; off; off >>= 1)
                acc[j] += __shfl_xor_sync(~0u, acc[j], off);
        }
        if (lane < 4){
            float g = acc[0];
            #pragma unroll
            for (int j = 1; j < 4; j++) if (lane == j) g = acc[j];
            sG[4*warp + lane] = g;
        }
        __syncthreads();

        if (tid < 16){
            const float* zz = zr + (t & 1)*64;
            float iv = sigf (sG[tid]      + zz[tid]);
            float fv = sigf (sG[16 + tid] + zz[16 + tid]);
            float gv = tanhf(sG[32 + tid] + zz[32 + tid]);
            float ov = sigf (sG[48 + tid] + zz[48 + tid]);
            cc = fv*cc + iv*gv;
            g_h[layer][t][b*16 + tid] = ov * tanhf(cc);
        }
        if (warp == 0){
            __syncwarp();
            if (lane == 0) st_rel(&g_flag[layer][b][0], t + 1);
        }

        // phase E: zr for t+1 from h^{l-1}_{t+1} (flag already verified)
        if (t + 1 < TS){
            const float* hp = &g_h[layer-1][t+1][0];
            float4 pv[4];
            #pragma unroll
            for (int c = 0; c < 4; c++)
                pv[c] = __ldcg(reinterpret_cast<const float4*>(hp + 128*c + 4*lane));
            float a2[4];
            #pragma unroll
            for (int j = 0; j < 4; j++){
                const float* wr = WI + (4*warp + j)*512 + 4*lane;
                float a = 0.0f;
                #pragma unroll
                for (int c = 0; c < 4; c++){
                    float4 w = *reinterpret_cast<const float4*>(wr + 128*c);
                    a = fmaf(w.x, pv[c].x, a); a = fmaf(w.y, pv[c].y, a);
                    a = fmaf(w.z, pv[c].z, a); a = fmaf(w.w, pv[c].w, a);
                }
                #pragma unroll
                for (int off = 16; off; off >>= 1) a += __shfl_xor_sync(~0u, a, off);
                a2[j] = a;
            }
            if (lane < 4){
                float g = a2[0];
                #pragma unroll
                for (int j = 1; j < 4; j++) if (lane == j) g = a2[j];
                zr[((t+1) & 1)*64 + 4*warp + lane] = g + sB[4*warp + lane];
            }
        }
    }
}

__global__ void __launch_bounds__(NT, 1) lstm_kernel(
    const float* __restrict__ x,
    const float* __restrict__ w_ih0, const float* __restrict__ w_hh0,
    const float* __restrict__ b_ih0, const float* __restrict__ b_hh0,
    const float* __restrict__ w_ih,  const float* __restrict__ w_hh,
    const float* __restrict__ b_ih,  const float* __restrict__ b_hh)
{
    extern __shared__ float sm[];
    int bid = blockIdx.x;
    if (bid < NB0){
        run_l0(bid, x, w_ih0, w_hh0, b_ih0, b_hh0, sm);
    } else {
        int r = bid - NB0;
        int layer = 1 + (r >> 5);
        int b = r & 31;
        size_t off = (size_t)(layer - 1) * (4*HD);
        run_l(layer, b, (layer == 1) ? NB0 : NB1,
              w_ih + off*HD, w_hh + off*HD, b_ih + off, b_hh + off, sm);
    }
}

// ---------------- epilogue + helpers ----------------

__global__ void k_zero(){
    int i = blockIdx.x*blockDim.x + threadIdx.x;
    if (i < NL*32*32) (&g_flag[0][0][0])[i] = 0;
}

__global__ void k_dummy(){ if (threadIdx.x == 0) g_dummy = blockIdx.x; }

__global__ void k_e(const float* __restrict__ wlin, const float* __restrict__ blin){
    int t = blockIdx.x;
    int tid = threadIdx.x;
    float a = 0.0f;
    for (int j = tid; j < HD; j += 128) a += g_h[NL-1][t][j] * wlin[j];
    #pragma unroll
    for (int off = 16; off; off >>= 1) a += __shfl_xor_sync(~0u, a, off);
    __shared__ float sr[4];
    if ((tid & 31) == 0) sr[tid >> 5] = a;
    __syncthreads();
    if (tid == 0) g_z[t] = tanhf(sr[0] + sr[1] + sr[2] + sr[3] + blin[0]);
}

__global__ void k_softmax(){
    int tid = threadIdx.x;
    __shared__ float sr[32];
    __shared__ float sbc;
    float z1 = g_z[tid], z2 = g_z[tid + 1024];
    float m = fmaxf(z1, z2);
    #pragma unroll
    for (int off = 16; off; off >>= 1) m = fmaxf(m, __shfl_xor_sync(~0u, m, off));
    if ((tid & 31) == 0) sr[tid >> 5] = m;
    __syncthreads();
    if (tid < 32){
        float v = sr[tid];
        #pragma unroll
        for (int off = 16; off; off >>= 1) v = fmaxf(v, __shfl_xor_sync(~0u, v, off));
        if (tid == 0) sbc = v;
    }
    __syncthreads();
    float mm = sbc;
    float e1 = expf(z1 - mm), e2 = expf(z2 - mm);
    float s = e1 + e2;
    #pragma unroll
    for (int off = 16; off; off >>= 1) s += __shfl_xor_sync(~0u, s, off);
    __syncthreads();
    if ((tid & 31) == 0) sr[tid >> 5] = s;
    __syncthreads();
    if (tid < 32){
        float v = sr[tid];
        #pragma unroll
        for (int off = 16; off; off >>= 1) v += __shfl_xor_sync(~0u, v, off);
        if (tid == 0) sbc = v;
    }
    __syncthreads();
    float inv = 1.0f / (sbc * (float)TS);
    g_wt[tid]        = e1 * inv;
    g_wt[tid + 1024] = e2 * inv;
}

__global__ void k_part(){
    int bb = blockIdx.x, tid = threadIdx.x;
    float a = 0.0f;
    int t0 = bb * 64;
    #pragma unroll 4
    for (int t = t0; t < t0 + 64; ++t) a += g_wt[t] * g_h[NL-1][t][tid];
    g_part[bb][tid] = a;
}

__global__ void k_final(float* __restrict__ out){
    int tid = threadIdx.x;
    float a = 0.0f;
    #pragma unroll
    for (int bb = 0; bb < 32; ++bb) a += g_part[bb][tid];
    out[tid] = a;
}

extern "C" void kernel_launch(void* const* d_in, const int* in_sizes, int n_in,
                              void* d_out, int out_size)
{
    const float* x     = (const float*)d_in[0];
    const float* w_ih0 = (const float*)d_in[1];
    const float* w_hh0 = (const float*)d_in[2];
    const float* b_ih0 = (const float*)d_in[3];
    const float* b_hh0 = (const float*)d_in[4];
    const float* w_ih  = (const float*)d_in[5];
    const float* w_hh  = (const float*)d_in[6];
    const float* b_ih  = (const float*)d_in[7];
    const float* b_hh  = (const float*)d_in[8];
    const float* w_lin = (const float*)d_in[9];
    const float* b_lin = (const float*)d_in[10];

    cudaFuncSetAttribute(lstm_kernel, cudaFuncAttributeMaxDynamicSharedMemorySize, SMEM_BYTES);

    k_zero<<<(NL*32*32 + 255)/256, 256>>>();
    k_dummy<<<1, 32>>>();               // keep lstm_kernel as the 4th launch
    k_dummy<<<1, 32>>>();               // so ncu's capture window hits it
    lstm_kernel<<<TOTAL_BLOCKS, NT, SMEM_BYTES>>>(x, w_ih0, w_hh0, b_ih0, b_hh0,
                                                  w_ih, w_hh, b_ih, b_hh);
    k_e<<<TS, 128>>>(w_lin, b_lin);
    k_softmax<<<1, 1024>>>();
    k_part<<<32, 512>>>();
    k_final<<<1, 512>>>((float*)d_out);
}